// round 15
// baseline (speedup 1.0000x reference)
#include <cuda_runtime.h>
#include <cuda_bf16.h>
#include <cuda_fp16.h>
#include <mma.h>

using namespace nvcuda;

// Problem constants (GATLayer): V=100000, E=1600000, Fin=128, H=4, Cout=32
#define FIN   128
#define HC    128   // H*Cout
#define NHEAD 4
#define MAXV  100000
#define MAXE  1600000
#define SCAN_BLK 1024

// -------- scratch (static device globals; allocation-free rule) --------
__device__ __align__(16) __half g_z[MAXV * HC];       // 25.6 MB (fp16 z)
__device__ __align__(16) float g_ssrc[MAXV * NHEAD];
__device__ __align__(16) float g_sdst[MAXV * NHEAD];
__device__ int g_deg[MAXV];
__device__ int g_off[MAXV + 1];
__device__ int g_rank[MAXE];
__device__ int g_srcs[MAXE];
__device__ int g_is32;

// -------- helpers --------
__device__ __forceinline__ float lrelu(float v) {
    return fmaxf(v, 0.2f * v);   // branchless LeakyReLU(0.2)
}

typedef unsigned long long u64;
__device__ __forceinline__ void ffma2(u64& d, u64 a, u64 b) {
    asm("fma.rn.f32x2 %0, %1, %2, %0;" : "+l"(d) : "l"(a), "l"(b));
}
__device__ __forceinline__ u64 pack2(float x) {
    u64 r; asm("mov.b64 %0, {%1, %1};" : "=l"(r) : "f"(x)); return r;
}
__device__ __forceinline__ u64 pack2f(float lo, float hi) {
    u64 r; asm("mov.b64 %0, {%1, %2};" : "=l"(r) : "f"(lo), "f"(hi)); return r;
}
__device__ __forceinline__ void unpack2(u64 p, float& lo, float& hi) {
    asm("mov.b64 {%0, %1}, %2;" : "=f"(lo), "=f"(hi) : "l"(p));
}

// ======================================================================
// detect_zero: self-contained dtype probe + deg zeroing.
// One warp of block 0 samples 256 odd 32-bit words: all-zero => int64
// (values < 2^31 so high words are 0); any nonzero => int32.
// Writes g_is32 unconditionally each run -> deterministic, no reset.
// ======================================================================
__global__ void detect_zero_kernel(const unsigned int* __restrict__ w,
                                   int n_words, int V) {
    int i = blockIdx.x * blockDim.x + threadIdx.x;
    if (i < V) g_deg[i] = 0;
    if (blockIdx.x == 0 && threadIdx.x < 32) {
        unsigned int any = 0;
        for (int j = 2 * threadIdx.x + 1; j < n_words && j < 512; j += 64)
            any |= w[j];
#pragma unroll
        for (int o = 16; o > 0; o >>= 1)
            any |= __shfl_xor_sync(0xffffffffu, any, o);
        if (threadIdx.x == 0) g_is32 = (any != 0u) ? 1 : 0;
    }
}

// ======================================================================
// hist: degree histogram + per-edge rank capture (the atomic's return
// value IS the edge's slot in its dst segment). 4 edges per thread —
// 4 independent atomic chains for latency hiding.
// ======================================================================
__global__ void hist_kernel(const void* __restrict__ ei, int E) {
    int i = blockIdx.x * blockDim.x + threadIdx.x;   // quad index
    int e = 4 * i;
    if (e >= E) return;
    int d[4];
    if (g_is32) {
        const int* p = (const int*)ei + E + e;
        int2 a = *(const int2*)p;
        d[0] = a.x; d[1] = a.y;
        if (e + 2 < E) { int2 b = *(const int2*)(p + 2); d[2] = b.x; d[3] = b.y; }
    } else {
        const long long* p = (const long long*)ei + E + e;
        longlong2 a = *(const longlong2*)p;
        d[0] = (int)a.x; d[1] = (int)a.y;
        if (e + 2 < E) {
            longlong2 b = *(const longlong2*)(p + 2);
            d[2] = (int)b.x; d[3] = (int)b.y;
        }
    }
    int r[4];
#pragma unroll
    for (int t = 0; t < 4; t++)
        r[t] = (e + t < E) ? atomicAdd(&g_deg[d[t]], 1) : 0;
#pragma unroll
    for (int t = 0; t < 4; t++)
        if (e + t < E) g_rank[e + t] = r[t];
}

// Single-kernel scan: each block independently sums deg[0..base)
// (deg = 400KB, L2-hot), then block-local exclusive scan. No
// inter-block dependency (the R11 lookback lesson).
__global__ void scan_kernel(int V) {
    __shared__ int sh[SCAN_BLK];
    int t = threadIdx.x;
    int bid = blockIdx.x;
    int base = bid * SCAN_BLK;

    int pre = 0;
    for (int q = t; q < base; q += SCAN_BLK) pre += g_deg[q];
    sh[t] = pre;
    __syncthreads();
#pragma unroll
    for (int s = SCAN_BLK / 2; s > 0; s >>= 1) {
        if (t < s) sh[t] += sh[t + s];
        __syncthreads();
    }
    int boff = sh[0];
    __syncthreads();

    int v = base + t;
    int x = (v < V) ? g_deg[v] : 0;
    sh[t] = x;
    __syncthreads();
#pragma unroll
    for (int off = 1; off < SCAN_BLK; off <<= 1) {
        int u = (t >= off) ? sh[t - off] : 0;
        __syncthreads();
        sh[t] += u;
        __syncthreads();
    }
    int excl = sh[t] - x + boff;
    if (v < V) {
        g_off[v] = excl;
        if (v == V - 1) g_off[V] = excl + x;
    }
}

// scatter: ATOMIC-FREE, 4 edges per thread. position = off[dst]+rank[e].
// 4 independent gather/store chains per thread for latency hiding.
__global__ void scatter_kernel(const void* __restrict__ ei, int E) {
    int i = blockIdx.x * blockDim.x + threadIdx.x;   // quad index
    int e = 4 * i;
    if (e >= E) return;
    int s[4], d[4];
    if (g_is32) {
        const int* p = (const int*)ei;
        int2 sa = *(const int2*)(p + e);
        int2 da = *(const int2*)(p + E + e);
        s[0] = sa.x; s[1] = sa.y; d[0] = da.x; d[1] = da.y;
        if (e + 2 < E) {
            int2 sb = *(const int2*)(p + e + 2);
            int2 db = *(const int2*)(p + E + e + 2);
            s[2] = sb.x; s[3] = sb.y; d[2] = db.x; d[3] = db.y;
        }
    } else {
        const long long* p = (const long long*)ei;
        longlong2 sa = *(const longlong2*)(p + e);
        longlong2 da = *(const longlong2*)(p + E + e);
        s[0] = (int)sa.x; s[1] = (int)sa.y; d[0] = (int)da.x; d[1] = (int)da.y;
        if (e + 2 < E) {
            longlong2 sb = *(const longlong2*)(p + e + 2);
            longlong2 db = *(const longlong2*)(p + E + e + 2);
            s[2] = (int)sb.x; s[3] = (int)sb.y; d[2] = (int)db.x; d[3] = (int)db.y;
        }
    }
    int rk[4], of[4];
#pragma unroll
    for (int t = 0; t < 4; t++)
        rk[t] = (e + t < E) ? g_rank[e + t] : 0;
#pragma unroll
    for (int t = 0; t < 4; t++)
        of[t] = (e + t < E) ? g_off[d[t]] : 0;
#pragma unroll
    for (int t = 0; t < 4; t++)
        if (e + t < E) g_srcs[of[t] + rk[t]] = s[t];
}

// ======================================================================
// GEMM: z = x @ W via fp16 tensor cores (HMMA, fp32 accumulate).
// BM=64, BN=128(full), BK=16, 256 threads = 8 warps.
// Warp (wr,wc): rows [wr*32,+32) x cols [wc*32,+32) as 2x2 wmma frags.
// Epilogue: frags -> per-warp smem scratch, per-lane row read ->
// head score (warp col block == one head) + fp16 z write.
// ======================================================================
#define BM 64
#define BK 16
#define XPAD 8
#define WPAD 8
#define SLD 36

__global__ void __launch_bounds__(256, 1)
gemm_kernel(const float* __restrict__ x,
            const float* __restrict__ W,
            const float* __restrict__ a_src,
            const float* __restrict__ a_dst, int V) {
    __shared__ __align__(16) __half xs[BM][BK + XPAD];
    __shared__ __align__(16) __half Wsm[BK][HC + WPAD];
    __shared__ __align__(16) float scratch[8][32][SLD];

    int tid = threadIdx.x;
    int wid = tid >> 5, lane = tid & 31;
    int wr = wid >> 2, wc = wid & 3;
    int row0 = blockIdx.x * BM;

    wmma::fragment<wmma::accumulator, 16, 16, 16, float> cf[2][2];
#pragma unroll
    for (int i = 0; i < 2; i++)
#pragma unroll
        for (int j = 0; j < 2; j++) wmma::fill_fragment(cf[i][j], 0.f);

    for (int kb = 0; kb < FIN; kb += BK) {
        {
            int r = tid >> 2, c4 = tid & 3;
            float4 v = make_float4(0.f, 0.f, 0.f, 0.f);
            if (row0 + r < V)
                v = *(const float4*)&x[(size_t)(row0 + r) * FIN + kb + c4 * 4];
            __half2* dp = (__half2*)&xs[r][c4 * 4];
            dp[0] = __floats2half2_rn(v.x, v.y);
            dp[1] = __floats2half2_rn(v.z, v.w);
        }
#pragma unroll
        for (int i = 0; i < 2; i++) {
            int f = i * 256 + tid;
            int r = f >> 5, c4 = f & 31;
            float4 v = *(const float4*)&W[(kb + r) * HC + c4 * 4];
            __half2* dp = (__half2*)&Wsm[r][c4 * 4];
            dp[0] = __floats2half2_rn(v.x, v.y);
            dp[1] = __floats2half2_rn(v.z, v.w);
        }
        __syncthreads();

        wmma::fragment<wmma::matrix_a, 16, 16, 16, __half, wmma::row_major> af[2];
        wmma::fragment<wmma::matrix_b, 16, 16, 16, __half, wmma::row_major> bf[2];
#pragma unroll
        for (int i = 0; i < 2; i++)
            wmma::load_matrix_sync(af[i], &xs[wr * 32 + i * 16][0], BK + XPAD);
#pragma unroll
        for (int j = 0; j < 2; j++)
            wmma::load_matrix_sync(bf[j], &Wsm[0][wc * 32 + j * 16], HC + WPAD);
#pragma unroll
        for (int i = 0; i < 2; i++)
#pragma unroll
            for (int j = 0; j < 2; j++)
                wmma::mma_sync(cf[i][j], af[i], bf[j], cf[i][j]);
        __syncthreads();
    }

#pragma unroll
    for (int i = 0; i < 2; i++)
#pragma unroll
        for (int j = 0; j < 2; j++)
            wmma::store_matrix_sync(&scratch[wid][i * 16][j * 16], cf[i][j],
                                    SLD, wmma::mem_row_major);
    __syncwarp();

    int h = wc;
    int r = row0 + wr * 32 + lane;

    float vals[32];
#pragma unroll
    for (int q = 0; q < 8; q++) {
        float4 v = *(float4*)&scratch[wid][lane][q * 4];
        vals[q * 4 + 0] = v.x; vals[q * 4 + 1] = v.y;
        vals[q * 4 + 2] = v.z; vals[q * 4 + 3] = v.w;
    }
    float ps = 0.f, pd = 0.f;
#pragma unroll
    for (int c = 0; c < 32; c++) {
        ps += vals[c] * __ldg(&a_src[h * 32 + c]);
        pd += vals[c] * __ldg(&a_dst[h * 32 + c]);
    }

    if (r < V) {
        __half2 hp[16];
#pragma unroll
        for (int q = 0; q < 16; q++)
            hp[q] = __floats2half2_rn(vals[2 * q], vals[2 * q + 1]);
        uint4* dst = (uint4*)&g_z[(size_t)r * HC + wc * 32];
#pragma unroll
        for (int q = 0; q < 4; q++) dst[q] = ((uint4*)hp)[q];
        g_ssrc[r * 4 + h] = ps;
        g_sdst[r * 4 + h] = pd;
    }
}

// ======================================================================
// Aggregation: ONE warp per dst, unroll-8 CSR walk (R10 winner).
// Broadcast srcs loads, fp16 z gather (256B/warp/edge), packed f32x2
// accumulate, fused softmax-normalize + ELU. 512-thread blocks.
// ======================================================================
__global__ void agg_kernel(float* __restrict__ out, int V) {
    int d = (blockIdx.x * blockDim.x + threadIdx.x) >> 5;
    int lane = threadIdx.x & 31;
    if (d >= V) return;

    int beg = g_off[d], end = g_off[d + 1];
    int h = lane >> 3;
    float sd = g_sdst[d * 4 + h];

    u64 acc01 = 0ull, acc23 = 0ull;
    float den = 0.f;

    int e = beg;
    for (; e + 8 <= end; e += 8) {
        int s[8];
#pragma unroll
        for (int t = 0; t < 8; t++) s[t] = __ldg(&g_srcs[e + t]);  // broadcast
#pragma unroll
        for (int t = 0; t < 8; t++) {
            float w = __expf(lrelu(__ldg(&g_ssrc[s[t] * 4 + h]) + sd));
            den += w;
            u64 wp = pack2(w);
            uint2 raw = *(const uint2*)&g_z[(size_t)s[t] * HC + lane * 4];
            float2 f0 = __half22float2(*(__half2*)&raw.x);
            float2 f1 = __half22float2(*(__half2*)&raw.y);
            ffma2(acc01, wp, pack2f(f0.x, f0.y));
            ffma2(acc23, wp, pack2f(f1.x, f1.y));
        }
    }
    for (; e < end; e++) {
        int s = __ldg(&g_srcs[e]);
        float w = __expf(lrelu(__ldg(&g_ssrc[s * 4 + h]) + sd));
        den += w;
        u64 wp = pack2(w);
        uint2 raw = *(const uint2*)&g_z[(size_t)s * HC + lane * 4];
        float2 f0 = __half22float2(*(__half2*)&raw.x);
        float2 f1 = __half22float2(*(__half2*)&raw.y);
        ffma2(acc01, wp, pack2f(f0.x, f0.y));
        ffma2(acc23, wp, pack2f(f1.x, f1.y));
    }

    float4 acc;
    unpack2(acc01, acc.x, acc.y);
    unpack2(acc23, acc.z, acc.w);

    float inv = 1.f / (den + 1e-9f);
    acc.x *= inv; acc.y *= inv; acc.z *= inv; acc.w *= inv;
    acc.x = acc.x > 0.f ? acc.x : expm1f(acc.x);
    acc.y = acc.y > 0.f ? acc.y : expm1f(acc.y);
    acc.z = acc.z > 0.f ? acc.z : expm1f(acc.z);
    acc.w = acc.w > 0.f ? acc.w : expm1f(acc.w);
    *(float4*)&out[(size_t)d * HC + lane * 4] = acc;
}

// ======================================================================
extern "C" void kernel_launch(void* const* d_in, const int* in_sizes, int n_in,
                              void* d_out, int out_size) {
    const float* x     = (const float*)d_in[0];
    const void*  ei    = d_in[1];
    const float* W     = (const float*)d_in[2];
    const float* a_src = (const float*)d_in[3];
    const float* a_dst = (const float*)d_in[4];
    float* out = (float*)d_out;

    int V = in_sizes[0] / FIN;
    int E = in_sizes[1] / 2;
    int nb = (V + SCAN_BLK - 1) / SCAN_BLK;

    // Side stream + fork/join events (created per call; kernel_launch only
    // runs a few times — eager + capture. No device memory involved.)
    cudaStream_t s1;
    cudaStreamCreateWithFlags(&s1, cudaStreamNonBlocking);
    cudaEvent_t ev_fork, ev_join;
    cudaEventCreateWithFlags(&ev_fork, cudaEventDisableTiming);
    cudaEventCreateWithFlags(&ev_join, cudaEventDisableTiming);

    // fork: side stream runs the CSR pipeline (4 kernels, scatter atomic-free)
    cudaEventRecord(ev_fork, 0);
    cudaStreamWaitEvent(s1, ev_fork, 0);

    int scan_words = 2 * E;
    if (scan_words > 512) scan_words = 512;

    detect_zero_kernel<<<(V + 255) / 256, 256, 0, s1>>>(
        (const unsigned int*)ei, scan_words, V);
    int quads = (E + 3) / 4;
    hist_kernel<<<(quads + 255) / 256, 256, 0, s1>>>(ei, E);
    scan_kernel<<<nb, SCAN_BLK, 0, s1>>>(V);
    scatter_kernel<<<(quads + 255) / 256, 256, 0, s1>>>(ei, E);
    cudaEventRecord(ev_join, s1);

    // main stream: tensor-core GEMM (independent), then join, then agg
    gemm_kernel<<<(V + BM - 1) / BM, 256>>>(x, W, a_src, a_dst, V);
    cudaStreamWaitEvent(0, ev_join, 0);
    agg_kernel<<<(V + 15) / 16, 512>>>(out, V);
}

// round 16
// speedup vs baseline: 1.0306x; 1.0306x over previous
#include <cuda_runtime.h>
#include <cuda_bf16.h>
#include <cuda_fp16.h>
#include <mma.h>

using namespace nvcuda;

// Problem constants (GATLayer): V=100000, E=1600000, Fin=128, H=4, Cout=32
#define FIN   128
#define HC    128   // H*Cout
#define NHEAD 4
#define MAXV  100000
#define MAXE  1600000
#define SCAN_BLK 1024

// -------- scratch (static device globals; allocation-free rule) --------
__device__ __align__(16) __half g_z[MAXV * HC];       // 25.6 MB (fp16 z)
__device__ __align__(16) float g_ssrc[MAXV * NHEAD];
__device__ __align__(16) float g_sdst[MAXV * NHEAD];
__device__ int g_deg[MAXV];
__device__ int g_off[MAXV + 1];
__device__ int g_rank[MAXE];
__device__ int g_srcs[MAXE];
__device__ int g_is32;

// -------- helpers --------
__device__ __forceinline__ float lrelu(float v) {
    return fmaxf(v, 0.2f * v);   // branchless LeakyReLU(0.2)
}

typedef unsigned long long u64;
__device__ __forceinline__ void ffma2(u64& d, u64 a, u64 b) {
    asm("fma.rn.f32x2 %0, %1, %2, %0;" : "+l"(d) : "l"(a), "l"(b));
}
__device__ __forceinline__ u64 pack2(float x) {
    u64 r; asm("mov.b64 %0, {%1, %1};" : "=l"(r) : "f"(x)); return r;
}
__device__ __forceinline__ u64 pack2f(float lo, float hi) {
    u64 r; asm("mov.b64 %0, {%1, %2};" : "=l"(r) : "f"(lo), "f"(hi)); return r;
}
__device__ __forceinline__ void unpack2(u64 p, float& lo, float& hi) {
    asm("mov.b64 {%0, %1}, %2;" : "=f"(lo), "=f"(hi) : "l"(p));
}

// ======================================================================
// detect_zero: self-contained dtype probe + deg zeroing.
// One warp of block 0 samples 256 odd 32-bit words: all-zero => int64
// (values < 2^31 so high words are 0); any nonzero => int32.
// Writes g_is32 unconditionally each run -> deterministic, no reset.
// ======================================================================
__global__ void detect_zero_kernel(const unsigned int* __restrict__ w,
                                   int n_words, int V) {
    int i = blockIdx.x * blockDim.x + threadIdx.x;
    if (i < V) g_deg[i] = 0;
    if (blockIdx.x == 0 && threadIdx.x < 32) {
        unsigned int any = 0;
        for (int j = 2 * threadIdx.x + 1; j < n_words && j < 512; j += 64)
            any |= w[j];
#pragma unroll
        for (int o = 16; o > 0; o >>= 1)
            any |= __shfl_xor_sync(0xffffffffu, any, o);
        if (threadIdx.x == 0) g_is32 = (any != 0u) ? 1 : 0;
    }
}

// ======================================================================
// hist: degree histogram + per-edge rank capture (the atomic's return
// value IS the edge's slot within its dst segment — save it so scatter
// needs no atomics). 2 edges per thread (max grid = max latency hiding;
// R15 showed 4/thread hurts via occupancy).
// ======================================================================
__global__ void hist_kernel(const void* __restrict__ ei, int E) {
    int i = blockIdx.x * blockDim.x + threadIdx.x;   // pair index
    int e = 2 * i;
    if (e >= E) return;
    int d0, d1;
    if (g_is32) {
        int2 p = *(const int2*)((const int*)ei + E + e);
        d0 = p.x; d1 = p.y;
    } else {
        longlong2 p = *(const longlong2*)((const long long*)ei + E + e);
        d0 = (int)p.x; d1 = (int)p.y;
    }
    int r0 = atomicAdd(&g_deg[d0], 1);
    int r1 = (e + 1 < E) ? atomicAdd(&g_deg[d1], 1) : 0;
    g_rank[e] = r0;
    if (e + 1 < E) g_rank[e + 1] = r1;
}

// Single-kernel scan: each block independently sums deg[0..base)
// (deg = 400KB, L2-hot), then block-local exclusive scan. No
// inter-block dependency (the R11 lookback lesson).
__global__ void scan_kernel(int V) {
    __shared__ int sh[SCAN_BLK];
    int t = threadIdx.x;
    int bid = blockIdx.x;
    int base = bid * SCAN_BLK;

    int pre = 0;
    for (int q = t; q < base; q += SCAN_BLK) pre += g_deg[q];
    sh[t] = pre;
    __syncthreads();
#pragma unroll
    for (int s = SCAN_BLK / 2; s > 0; s >>= 1) {
        if (t < s) sh[t] += sh[t + s];
        __syncthreads();
    }
    int boff = sh[0];
    __syncthreads();

    int v = base + t;
    int x = (v < V) ? g_deg[v] : 0;
    sh[t] = x;
    __syncthreads();
#pragma unroll
    for (int off = 1; off < SCAN_BLK; off <<= 1) {
        int u = (t >= off) ? sh[t - off] : 0;
        __syncthreads();
        sh[t] += u;
        __syncthreads();
    }
    int excl = sh[t] - x + boff;
    if (v < V) {
        g_off[v] = excl;
        if (v == V - 1) g_off[V] = excl + x;
    }
}

// scatter: ATOMIC-FREE. position = off[dst] + rank[e]; rank loads are
// coalesced, off loads are 1-sector gathers, store is fire-and-forget.
// 2 edges per thread (R14 best shape).
__global__ void scatter_kernel(const void* __restrict__ ei, int E) {
    int i = blockIdx.x * blockDim.x + threadIdx.x;   // pair index
    int e = 2 * i;
    if (e >= E) return;
    int s0, s1, d0, d1;
    if (g_is32) {
        const int* p = (const int*)ei;
        int2 sp = *(const int2*)(p + e);
        int2 dp = *(const int2*)(p + E + e);
        s0 = sp.x; s1 = sp.y; d0 = dp.x; d1 = dp.y;
    } else {
        const long long* p = (const long long*)ei;
        longlong2 sp = *(const longlong2*)(p + e);
        longlong2 dp = *(const longlong2*)(p + E + e);
        s0 = (int)sp.x; s1 = (int)sp.y; d0 = (int)dp.x; d1 = (int)dp.y;
    }
    int2 rk = *(const int2*)&g_rank[e];          // coalesced 8B
    g_srcs[g_off[d0] + rk.x] = s0;
    if (e + 1 < E) g_srcs[g_off[d1] + rk.y] = s1;
}

// ======================================================================
// GEMM: z = x @ W via fp16 tensor cores (HMMA, fp32 accumulate).
// BM=64, BN=128(full), BK=16, 256 threads = 8 warps.
// Warp (wr,wc): rows [wr*32,+32) x cols [wc*32,+32) as 2x2 wmma frags.
// Epilogue: frags -> per-warp smem scratch, per-lane row read ->
// head score (warp col block == one head) + fp16 z write.
// ======================================================================
#define BM 64
#define BK 16
#define XPAD 8
#define WPAD 8
#define SLD 36

__global__ void __launch_bounds__(256, 1)
gemm_kernel(const float* __restrict__ x,
            const float* __restrict__ W,
            const float* __restrict__ a_src,
            const float* __restrict__ a_dst, int V) {
    __shared__ __align__(16) __half xs[BM][BK + XPAD];
    __shared__ __align__(16) __half Wsm[BK][HC + WPAD];
    __shared__ __align__(16) float scratch[8][32][SLD];

    int tid = threadIdx.x;
    int wid = tid >> 5, lane = tid & 31;
    int wr = wid >> 2, wc = wid & 3;
    int row0 = blockIdx.x * BM;

    wmma::fragment<wmma::accumulator, 16, 16, 16, float> cf[2][2];
#pragma unroll
    for (int i = 0; i < 2; i++)
#pragma unroll
        for (int j = 0; j < 2; j++) wmma::fill_fragment(cf[i][j], 0.f);

    for (int kb = 0; kb < FIN; kb += BK) {
        {
            int r = tid >> 2, c4 = tid & 3;
            float4 v = make_float4(0.f, 0.f, 0.f, 0.f);
            if (row0 + r < V)
                v = *(const float4*)&x[(size_t)(row0 + r) * FIN + kb + c4 * 4];
            __half2* dp = (__half2*)&xs[r][c4 * 4];
            dp[0] = __floats2half2_rn(v.x, v.y);
            dp[1] = __floats2half2_rn(v.z, v.w);
        }
#pragma unroll
        for (int i = 0; i < 2; i++) {
            int f = i * 256 + tid;
            int r = f >> 5, c4 = f & 31;
            float4 v = *(const float4*)&W[(kb + r) * HC + c4 * 4];
            __half2* dp = (__half2*)&Wsm[r][c4 * 4];
            dp[0] = __floats2half2_rn(v.x, v.y);
            dp[1] = __floats2half2_rn(v.z, v.w);
        }
        __syncthreads();

        wmma::fragment<wmma::matrix_a, 16, 16, 16, __half, wmma::row_major> af[2];
        wmma::fragment<wmma::matrix_b, 16, 16, 16, __half, wmma::row_major> bf[2];
#pragma unroll
        for (int i = 0; i < 2; i++)
            wmma::load_matrix_sync(af[i], &xs[wr * 32 + i * 16][0], BK + XPAD);
#pragma unroll
        for (int j = 0; j < 2; j++)
            wmma::load_matrix_sync(bf[j], &Wsm[0][wc * 32 + j * 16], HC + WPAD);
#pragma unroll
        for (int i = 0; i < 2; i++)
#pragma unroll
            for (int j = 0; j < 2; j++)
                wmma::mma_sync(cf[i][j], af[i], bf[j], cf[i][j]);
        __syncthreads();
    }

#pragma unroll
    for (int i = 0; i < 2; i++)
#pragma unroll
        for (int j = 0; j < 2; j++)
            wmma::store_matrix_sync(&scratch[wid][i * 16][j * 16], cf[i][j],
                                    SLD, wmma::mem_row_major);
    __syncwarp();

    int h = wc;
    int r = row0 + wr * 32 + lane;

    float vals[32];
#pragma unroll
    for (int q = 0; q < 8; q++) {
        float4 v = *(float4*)&scratch[wid][lane][q * 4];
        vals[q * 4 + 0] = v.x; vals[q * 4 + 1] = v.y;
        vals[q * 4 + 2] = v.z; vals[q * 4 + 3] = v.w;
    }
    float ps = 0.f, pd = 0.f;
#pragma unroll
    for (int c = 0; c < 32; c++) {
        ps += vals[c] * __ldg(&a_src[h * 32 + c]);
        pd += vals[c] * __ldg(&a_dst[h * 32 + c]);
    }

    if (r < V) {
        __half2 hp[16];
#pragma unroll
        for (int q = 0; q < 16; q++)
            hp[q] = __floats2half2_rn(vals[2 * q], vals[2 * q + 1]);
        uint4* dst = (uint4*)&g_z[(size_t)r * HC + wc * 32];
#pragma unroll
        for (int q = 0; q < 4; q++) dst[q] = ((uint4*)hp)[q];
        g_ssrc[r * 4 + h] = ps;
        g_sdst[r * 4 + h] = pd;
    }
}

// ======================================================================
// Aggregation: ONE warp per dst, unroll-8 CSR walk (R10/R14 winner).
// Broadcast srcs loads, fp16 z gather (256B/warp/edge), packed f32x2
// accumulate, fused softmax-normalize + ELU. 256-thread blocks.
// ======================================================================
__global__ void agg_kernel(float* __restrict__ out, int V) {
    int d = (blockIdx.x * blockDim.x + threadIdx.x) >> 5;
    int lane = threadIdx.x & 31;
    if (d >= V) return;

    int beg = g_off[d], end = g_off[d + 1];
    int h = lane >> 3;
    float sd = g_sdst[d * 4 + h];

    u64 acc01 = 0ull, acc23 = 0ull;
    float den = 0.f;

    int e = beg;
    for (; e + 8 <= end; e += 8) {
        int s[8];
#pragma unroll
        for (int t = 0; t < 8; t++) s[t] = __ldg(&g_srcs[e + t]);  // broadcast
#pragma unroll
        for (int t = 0; t < 8; t++) {
            float w = __expf(lrelu(__ldg(&g_ssrc[s[t] * 4 + h]) + sd));
            den += w;
            u64 wp = pack2(w);
            uint2 raw = *(const uint2*)&g_z[(size_t)s[t] * HC + lane * 4];
            float2 f0 = __half22float2(*(__half2*)&raw.x);
            float2 f1 = __half22float2(*(__half2*)&raw.y);
            ffma2(acc01, wp, pack2f(f0.x, f0.y));
            ffma2(acc23, wp, pack2f(f1.x, f1.y));
        }
    }
    for (; e < end; e++) {
        int s = __ldg(&g_srcs[e]);
        float w = __expf(lrelu(__ldg(&g_ssrc[s * 4 + h]) + sd));
        den += w;
        u64 wp = pack2(w);
        uint2 raw = *(const uint2*)&g_z[(size_t)s * HC + lane * 4];
        float2 f0 = __half22float2(*(__half2*)&raw.x);
        float2 f1 = __half22float2(*(__half2*)&raw.y);
        ffma2(acc01, wp, pack2f(f0.x, f0.y));
        ffma2(acc23, wp, pack2f(f1.x, f1.y));
    }

    float4 acc;
    unpack2(acc01, acc.x, acc.y);
    unpack2(acc23, acc.z, acc.w);

    float inv = 1.f / (den + 1e-9f);
    acc.x *= inv; acc.y *= inv; acc.z *= inv; acc.w *= inv;
    acc.x = acc.x > 0.f ? acc.x : expm1f(acc.x);
    acc.y = acc.y > 0.f ? acc.y : expm1f(acc.y);
    acc.z = acc.z > 0.f ? acc.z : expm1f(acc.z);
    acc.w = acc.w > 0.f ? acc.w : expm1f(acc.w);
    *(float4*)&out[(size_t)d * HC + lane * 4] = acc;
}

// ======================================================================
extern "C" void kernel_launch(void* const* d_in, const int* in_sizes, int n_in,
                              void* d_out, int out_size) {
    const float* x     = (const float*)d_in[0];
    const void*  ei    = d_in[1];
    const float* W     = (const float*)d_in[2];
    const float* a_src = (const float*)d_in[3];
    const float* a_dst = (const float*)d_in[4];
    float* out = (float*)d_out;

    int V = in_sizes[0] / FIN;
    int E = in_sizes[1] / 2;
    int nb = (V + SCAN_BLK - 1) / SCAN_BLK;

    // Side stream + fork/join events (created per call; kernel_launch only
    // runs a few times — eager + capture. No device memory involved.)
    cudaStream_t s1;
    cudaStreamCreateWithFlags(&s1, cudaStreamNonBlocking);
    cudaEvent_t ev_fork, ev_join;
    cudaEventCreateWithFlags(&ev_fork, cudaEventDisableTiming);
    cudaEventCreateWithFlags(&ev_join, cudaEventDisableTiming);

    // fork: side stream runs the CSR pipeline (4 kernels, scatter atomic-free)
    cudaEventRecord(ev_fork, 0);
    cudaStreamWaitEvent(s1, ev_fork, 0);

    int scan_words = 2 * E;
    if (scan_words > 512) scan_words = 512;

    detect_zero_kernel<<<(V + 255) / 256, 256, 0, s1>>>(
        (const unsigned int*)ei, scan_words, V);
    int pairs = (E + 1) / 2;
    hist_kernel<<<(pairs + 255) / 256, 256, 0, s1>>>(ei, E);
    scan_kernel<<<nb, SCAN_BLK, 0, s1>>>(V);
    scatter_kernel<<<(pairs + 255) / 256, 256, 0, s1>>>(ei, E);
    cudaEventRecord(ev_join, s1);

    // main stream: tensor-core GEMM (independent), then join, then agg
    gemm_kernel<<<(V + BM - 1) / BM, 256>>>(x, W, a_src, a_dst, V);
    cudaStreamWaitEvent(0, ev_join, 0);
    agg_kernel<<<(V + 7) / 8, 256>>>(out, V);
}